// round 6
// baseline (speedup 1.0000x reference)
#include <cuda_runtime.h>
#include <cstdint>
#include <cstddef>

#define BATCH  64
#define TSTEPS 1000
#define NG     2
#define HH     160      // hidden per group (STEP)
#define DD     320      // NG*HH
#define NGATE  640      // 4*HH
#define NCH    64
#define NF     5

// ---- recurrence config: 320 threads, 2 gate-columns per thread, f32x2 packed ----
#define RNT 320
#define RSK 88          // k-rows with weights in smem
#define RRK 72          // k-rows with weights in registers
#define PAIRS_S (RSK/2) // 44 ulonglong2 per thread (smem part)
#define PAIRS_R (RRK/2) // 36
#define REC_SMEM (PAIRS_S*RNT*16 + 2*HH*8)   // 225280 + 2560 = 227840 B

typedef unsigned long long ull;

#define FFMA2(d, a, b, c) asm("fma.rn.f32x2 %0, %1, %2, %3;" : "=l"(d) : "l"(a), "l"(b), "l"(c))
#define FADD2(d, a, b)    asm("add.rn.f32x2 %0, %1, %2;"     : "=l"(d) : "l"(a), "l"(b))
#define PACK2(d, x, y)    asm("mov.b64 %0, {%1, %2};"        : "=l"(d) : "f"(x), "f"(y))
#define UNPACK2(x, y, s)  asm("mov.b64 {%0, %1}, %2;"        : "=f"(x), "=f"(y) : "l"(s))

// ---------------- scratch (static device globals) ----------------
__device__ float g_x1[(size_t)BATCH * TSTEPS * DD];
__device__ float g_x2[(size_t)BATCH * TSTEPS * DD];
__device__ float g_gates[(size_t)BATCH * TSTEPS * NG * NGATE];
__device__ ulonglong2 g_wsm[NG * PAIRS_S * RNT];   // smem-part weights, paired (c0,c1)
__device__ ull        g_wrg[NG * RRK * RNT];       // reg-part weights, paired (c0,c1)

// ---------------- transpose: [B,C,T,F] -> [B*T, C*F] ----------------
__global__ void transpose_kernel(const float* __restrict__ in)
{
    size_t idx = (size_t)blockIdx.x * blockDim.x + threadIdx.x;
    if (idx >= (size_t)BATCH * NCH * TSTEPS * NF) return;
    int f = (int)(idx % NF);
    size_t r = idx / NF;
    int t = (int)(r % TSTEPS); r /= TSTEPS;
    int c = (int)(r % NCH);    r /= NCH;
    int b = (int)r;
    g_x1[((size_t)(b * TSTEPS + t)) * DD + c * NF + f] = in[idx];
}

// ---------------- weight prep: permute Whh into paired rec layout ----------------
// rec thread t = 2u+r owns columns c0=(2r)*HH+u (pair lane lo), c1=(2r+1)*HH+u (hi).
__global__ void prep_kernel(const float* __restrict__ Whh)
{
    int idx = blockIdx.x * blockDim.x + threadIdx.x;
    if (idx >= NG * HH * NGATE) return;
    int cidx = idx % NGATE;
    int k    = (idx / NGATE) % HH;
    int g    = idx / (NGATE * HH);
    float w = Whh[idx];
    int u = cidx % HH, q = cidx / HH;        // q: gate (i,f,g,o)
    int r = q >> 1, col = q & 1;             // col: pair lane
    int tt = 2 * u + r;
    if (k < RSK) {
        int p = k >> 1, sub = k & 1;
        ((float*)g_wsm)[(((size_t)(g * PAIRS_S + p) * RNT + tt) * 2 + sub) * 2 + col] = w;
    } else {
        int j = k - RSK;
        ((float*)g_wrg)[(((size_t)(g * RRK + j) * RNT + tt)) * 2 + col] = w;
    }
}

// ---------------- pre-GEMM: 128x64 tile, 256 threads, 8x4 per thread, f32x2 ----------
template <int STAGE>
__global__ __launch_bounds__(256) void pregemm_kernel(const float* __restrict__ W,
                                                      const float* __restrict__ bias)
{
    __shared__ float As[16][132];   // [k][m]
    __shared__ float Bs[16][64];    // [k][n]

    const float* X = (STAGE == 1) ? g_x1 : g_x2;

    const int m0 = blockIdx.x * 128;
    const int n0 = blockIdx.y * 64;
    const int g  = blockIdx.z;
    const int tid = threadIdx.x;
    const int tm = tid >> 4;
    const int tn = tid & 15;

    const int rowA = tid >> 1;
    const int kqA  = (tid & 1) * 8;
    const int kB   = tid >> 4;
    const int nqB  = (tid & 15) * 4;

    const float* Xp = X + (size_t)(m0 + rowA) * DD + g * HH + kqA;
    const float* Wp = W + (size_t)g * HH * NGATE + (size_t)kB * NGATE + n0 + nqB;

    ull acc[8][2];
    const ull z = 0ULL;
#pragma unroll
    for (int i = 0; i < 8; i++) { acc[i][0] = z; acc[i][1] = z; }

    for (int k0 = 0; k0 < HH; k0 += 16) {
        float4 x0 = *(const float4*)(Xp + k0);
        float4 x1 = *(const float4*)(Xp + k0 + 4);
        As[kqA + 0][rowA] = x0.x;
        As[kqA + 1][rowA] = x0.y;
        As[kqA + 2][rowA] = x0.z;
        As[kqA + 3][rowA] = x0.w;
        As[kqA + 4][rowA] = x1.x;
        As[kqA + 5][rowA] = x1.y;
        As[kqA + 6][rowA] = x1.z;
        As[kqA + 7][rowA] = x1.w;
        *(float4*)&Bs[kB][nqB] = *(const float4*)(Wp + (size_t)k0 * NGATE);
        __syncthreads();
#pragma unroll
        for (int k = 0; k < 16; k++) {
            float4 a0 = *(const float4*)&As[k][tm * 8];
            float4 a1 = *(const float4*)&As[k][tm * 8 + 4];
            ulonglong2 b2 = *(const ulonglong2*)&Bs[k][tn * 4];
            float av[8] = {a0.x, a0.y, a0.z, a0.w, a1.x, a1.y, a1.z, a1.w};
#pragma unroll
            for (int i = 0; i < 8; i++) {
                ull ad;
                PACK2(ad, av[i], av[i]);
                FFMA2(acc[i][0], ad, b2.x, acc[i][0]);
                FFMA2(acc[i][1], ad, b2.y, acc[i][1]);
            }
        }
        __syncthreads();
    }

    float4 bb = *(const float4*)(bias + g * NGATE + n0 + tn * 4);
    ull bb0, bb1;
    PACK2(bb0, bb.x, bb.y);
    PACK2(bb1, bb.z, bb.w);
#pragma unroll
    for (int i = 0; i < 8; i++) {
        int m = m0 + tm * 8 + i;
        ulonglong2 o;
        FADD2(o.x, acc[i][0], bb0);
        FADD2(o.y, acc[i][1], bb1);
        *(ulonglong2*)(g_gates + ((size_t)m * NG + g) * NGATE + n0 + tn * 4) = o;
    }
}

// ---------------- recurrence (f32x2 packed columns, dup-h) ----------------
// thread t=2u+r: pair = (gate 2r, gate 2r+1) of unit u. r=0 -> (i,f); r=1 -> (g,o).
template <int STAGE>
__global__ __launch_bounds__(RNT, 1) void rec_kernel(float* __restrict__ out)
{
    extern __shared__ char smraw[];
    ulonglong2* ws2 = (ulonglong2*)smraw;                    // [PAIRS_S][RNT]
    ull*        hd  = (ull*)(smraw + PAIRS_S * RNT * 16);    // [2][HH] (h,h) dup pairs

    const int t_ = threadIdx.x;
    const int u  = t_ >> 1;
    const int r  = t_ & 1;
    const int b  = blockIdx.x >> 1;
    const int g  = blockIdx.x & 1;

    // coalesced load of smem weight pairs
    const ulonglong2* wsrc = g_wsm + (size_t)g * PAIRS_S * RNT;
#pragma unroll 4
    for (int i = t_; i < PAIRS_S * RNT; i += RNT) ws2[i] = wsrc[i];

    // coalesced load of register weight pairs
    ull wr[RRK];
    const ull* wrsrc = g_wrg + (size_t)g * RRK * RNT + t_;
#pragma unroll
    for (int j = 0; j < RRK; j++) wr[j] = wrsrc[(size_t)j * RNT];

    hd[t_] = 0ULL;   // RNT == 2*HH: zeros both h buffers
    float c = 0.f;
    __syncthreads();

    const int c0 = (2 * r) * HH + u;
    const int c1 = (2 * r + 1) * HH + u;
    const float* grow = g_gates + ((size_t)b * TSTEPS) * NG * NGATE + (size_t)g * NGATE;
    ull gxp;
    PACK2(gxp, grow[c0], grow[c1]);
    int p = 0;

    const ulonglong2* ws_t = ws2 + t_;

    for (int t = 0; t < TSTEPS; t++) {
        float nx0 = 0.f, nx1 = 0.f;
        if (t + 1 < TSTEPS) {
            const float* gn = grow + (size_t)(t + 1) * NG * NGATE;
            nx0 = __ldg(gn + c0);
            nx1 = __ldg(gn + c1);
        }

        const ulonglong2* hp = (const ulonglong2*)(hd + p * HH);
        ull acc0 = gxp, acc1 = 0ULL, acc2 = 0ULL, acc3 = 0ULL;
#pragma unroll
        for (int pp = 0; pp < PAIRS_S; pp++) {
            ulonglong2 w = ws_t[(size_t)pp * RNT];
            ulonglong2 h = hp[pp];
            FFMA2(acc0, w.x, h.x, acc0);
            FFMA2(acc1, w.y, h.y, acc1);
        }
#pragma unroll
        for (int jj = 0; jj < PAIRS_R; jj++) {
            ulonglong2 h = hp[PAIRS_S + jj];
            FFMA2(acc2, wr[2 * jj], h.x, acc2);
            FFMA2(acc3, wr[2 * jj + 1], h.y, acc3);
        }
        FADD2(acc0, acc0, acc1);
        FADD2(acc2, acc2, acc3);
        FADD2(acc0, acc0, acc2);
        float lo, hi;
        UNPACK2(lo, hi, acc0);

        // r=0: lo=i-pre, hi=f-pre (both sigmoid)
        // r=1: lo=g-pre (tanh = 2*sigmoid(2x)-1), hi=o-pre (sigmoid)
        float z0 = r ? 2.f * lo : lo;
        float s0 = __fdividef(1.f, 1.f + __expf(-z0));
        float A0 = r ? fmaf(2.f, s0, -1.f) : s0;
        float A1 = __fdividef(1.f, 1.f + __expf(-hi));
        float X0 = __shfl_xor_sync(0xFFFFFFFFu, A0, 1);
        float X1 = __shfl_xor_sync(0xFFFFFFFFu, A1, 1);
        float gi = r ? X0 : A0;
        float gf = r ? X1 : A1;
        float gg = r ? A0 : X0;
        float go = r ? A1 : X1;
        c = fmaf(gf, c, gi * gg);
        float th = __fdividef(2.f, 1.f + __expf(-2.f * c)) - 1.f;
        float hval = go * th;

        if (r == 0) {
            ull hp2;
            PACK2(hp2, hval, hval);
            hd[(p ^ 1) * HH + u] = hp2;
            if (STAGE == 1) {
                int i5 = u / NF, f5 = u - i5 * NF;
                g_x2[((size_t)b * TSTEPS + t) * DD + i5 * 10 + g * NF + f5] = hval;
            } else {
                int d = g * HH + u;
                int cc = d / NF, f5 = d - cc * NF;
                out[(((size_t)b * NCH + cc) * TSTEPS + t) * NF + f5] = hval;
            }
        }
        __syncthreads();
        PACK2(gxp, nx0, nx1);
        p ^= 1;
    }
}

// ---------------- launch ----------------
extern "C" void kernel_launch(void* const* d_in, const int* in_sizes, int n_in,
                              void* d_out, int out_size)
{
    (void)in_sizes; (void)n_in; (void)out_size;
    const float* input = (const float*)d_in[0];
    const float* Wih1  = (const float*)d_in[1];
    const float* Whh1  = (const float*)d_in[2];
    const float* b1    = (const float*)d_in[3];
    const float* Wih2  = (const float*)d_in[4];
    const float* Whh2  = (const float*)d_in[5];
    const float* b2    = (const float*)d_in[6];
    float* out = (float*)d_out;

    cudaFuncSetAttribute(rec_kernel<1>, cudaFuncAttributeMaxDynamicSharedMemorySize, REC_SMEM);
    cudaFuncSetAttribute(rec_kernel<2>, cudaFuncAttributeMaxDynamicSharedMemorySize, REC_SMEM);

    const int n_in_elems = BATCH * NCH * TSTEPS * NF;
    const int n_w = NG * HH * NGATE;
    dim3 gg(BATCH * TSTEPS / 128, NGATE / 64, NG);

    transpose_kernel<<<(n_in_elems + 255) / 256, 256>>>(input);

    prep_kernel<<<(n_w + 255) / 256, 256>>>(Whh1);
    pregemm_kernel<1><<<gg, 256>>>(Wih1, b1);
    rec_kernel<1><<<BATCH * NG, RNT, REC_SMEM>>>(nullptr);

    prep_kernel<<<(n_w + 255) / 256, 256>>>(Whh2);
    pregemm_kernel<2><<<gg, 256>>>(Wih2, b2);
    rec_kernel<2><<<BATCH * NG, RNT, REC_SMEM>>>(out);
}